// round 10
// baseline (speedup 1.0000x reference)
#include <cuda_runtime.h>
#include <cuda_bf16.h>

#define NE 3
#define BB 256
#define TT 168
#define DE 32
#define UU 256
#define U3 768
#define HH 24
#define BT (BB*TT)

typedef unsigned long long ull;

__device__ __forceinline__ ull pack2(float lo, float hi){ ull r; asm("mov.b64 %0,{%1,%2};":"=l"(r):"f"(lo),"f"(hi)); return r; }
__device__ __forceinline__ void unpack2(ull v, float&lo, float&hi){ asm("mov.b64 {%0,%1},%2;":"=f"(lo),"=f"(hi):"l"(v)); }
__device__ __forceinline__ void fma2(ull&d, ull a, ull b){ asm("fma.rn.f32x2 %0,%1,%2,%0;":"+l"(d):"l"(a),"l"(b)); }

__device__ __forceinline__ float sigm(float x){ return __fdividef(1.f, 1.f + __expf(-x)); }
__device__ __forceinline__ float tanh_(float x){
    float e = __expf(-2.f*fabsf(x));
    float t = __fdividef(1.f-e, 1.f+e);
    return copysignf(t,x);
}
__device__ __forceinline__ float tanha(float x){ float y; asm("tanh.approx.f32 %0,%1;":"=f"(y):"f"(x)); return y; }
__device__ __forceinline__ float blo(unsigned pk){ return __uint_as_float(pk << 16); }
__device__ __forceinline__ float bhi(unsigned pk){ return __uint_as_float(pk & 0xffff0000u); }

// ---------------- device scratch ----------------
__device__ __align__(16) __nv_bfloat16 g_eoh[NE][BT][UU]; // enc_out bf16
__device__ __align__(16) __nv_bfloat16 g_pjh[NE][BT][UU]; // enc_proj bf16
__device__ __align__(16) float g_h[2][NE][BB][UU];        // encoder hidden ping-pong
__device__ __align__(16) float g_hd2[2][BB][UU];          // decoder hidden ping-pong
__device__ __align__(16) float g_c[BB][U3];
__device__ __align__(16) float g_q2[2][NE][BB][UU];       // q K-split partials
__device__ __align__(16) float g_dp2[8][BB][U3];          // decoder GRU K-split partials
__device__ __align__(16) float g_s1[BB][UU];
__device__ unsigned g_es[12];                             // encoder group counters
__device__ unsigned g_dcnt[32];                           // decoder fan-in counters

__global__ void k_init(){
    int i = blockIdx.x*256 + threadIdx.x;   // 768*256 = 196608
    ((float*)g_h)[i] = 0.f;                  // NE*BB*UU*2/2: zeros buffer 0 exactly
    if (i < BB*UU) ((float*)g_hd2)[i] = 0.f; // hd2[0]
    if (i < BB*U3) ((float*)g_c)[i]  = 0.f;
    if (i < 12)    g_es[i] = 0u;
    if (i < 32)    g_dcnt[i] = 0u;
}

// ---------------- encoder: SMEM-resident weights, 8-CTA group sync (unchanged) ----------------
#define E_SWU 0
#define E_SWX 24576
#define E_SH  27648
#define E_SXI 44544
#define E_TOT 46656

__global__ __launch_bounds__(256,1) void k_enc(const float* __restrict__ X, const float* __restrict__ W,
                                               const float* __restrict__ Uw, const float* __restrict__ bv){
    extern __shared__ float sm[];
    float* swU = sm + E_SWU;
    float* swX = sm + E_SWX;
    float* sh  = sm + E_SH;
    float* sxi = sm + E_SXI;

    const int cid = blockIdx.x;
    const int n = cid >> 5, rem = cid & 31;
    const int r0 = (rem >> 3) * 64, u0 = (rem & 7) * 32;
    const int gid = n*4 + (rem >> 3);
    const int tx = threadIdx.x, ul = tx & 31, grp = tx >> 5;

    for (int idx = tx; idx < 24576; idx += 256){
        int k = idx / 96, c = idx % 96;
        int g = c >> 5, cc = c & 31;
        swU[idx] = Uw[(size_t)n*UU*U3 + (size_t)k*U3 + g*256 + u0 + cc];
    }
    for (int idx = tx; idx < 3072; idx += 256){
        int k = idx / 96, c = idx % 96;
        int g = c >> 5, cc = c & 31;
        swX[idx] = W[(size_t)n*DE*U3 + (size_t)k*U3 + g*256 + u0 + cc];
    }
    const float bz = bv[n*U3 + u0+ul];
    const float br = bv[n*U3 + 256 + u0+ul];
    const float bn = bv[n*U3 + 512 + u0+ul];
    __syncthreads();

    __nv_bfloat16* eob = &g_eoh[n][0][0];

    for (int t = 0; t < TT; ++t){
        const float* hs = &g_h[t&1][n][0][0];
        #pragma unroll 8
        for (int i = 0; i < 64; ++i) sh[tx*66 + i] = __ldcg(hs + (size_t)(r0+i)*UU + tx);
        {
            int idx = tx;
            #pragma unroll
            for (int i = 0; i < 8; ++i, idx += 256){
                int row = idx >> 5, col = idx & 31;
                sxi[col*66 + row] = X[(((size_t)n*BB + r0+row)*TT + t)*DE + col];
            }
        }
        __syncthreads();

        ull az[4], ar[4], ax[4], ah[4];
        #pragma unroll
        for (int j=0;j<4;++j){ az[j]=pack2(bz,bz); ar[j]=pack2(br,br); ax[j]=pack2(bn,bn); ah[j]=pack2(0.f,0.f); }

        #pragma unroll 4
        for (int k = 0; k < 256; ++k){
            const float* wrow = swU + k*96;
            float wza = wrow[ul], wra = wrow[32+ul], wna = wrow[64+ul];
            ull wz = pack2(wza,wza), wr = pack2(wra,wra), wn = pack2(wna,wna);
            const float* hrow = sh + k*66 + grp*8;
            #pragma unroll
            for (int j=0;j<4;++j){
                ull h2 = *(const ull*)&hrow[2*j];
                fma2(az[j],h2,wz); fma2(ar[j],h2,wr); fma2(ah[j],h2,wn);
            }
        }
        #pragma unroll 4
        for (int k = 0; k < 32; ++k){
            const float* wrow = swX + k*96;
            float wza = wrow[ul], wra = wrow[32+ul], wna = wrow[64+ul];
            ull wz = pack2(wza,wza), wr = pack2(wra,wra), wn = pack2(wna,wna);
            const float* xrow = sxi + k*66 + grp*8;
            #pragma unroll
            for (int j=0;j<4;++j){
                ull x2 = *(const ull*)&xrow[2*j];
                fma2(az[j],x2,wz); fma2(ar[j],x2,wr); fma2(ax[j],x2,wn);
            }
        }

        float* hd = &g_h[(t+1)&1][n][0][0];
        #pragma unroll
        for (int j=0;j<4;++j){
            int rl = grp*8 + 2*j;
            float z0,z1,rg0,rg1,x0,x1,hh0,hh1;
            unpack2(az[j],z0,z1); unpack2(ar[j],rg0,rg1); unpack2(ax[j],x0,x1); unpack2(ah[j],hh0,hh1);
            float hp0 = sh[(u0+ul)*66 + rl];
            float hp1 = sh[(u0+ul)*66 + rl + 1];
            z0=sigm(z0); z1=sigm(z1); rg0=sigm(rg0); rg1=sigm(rg1);
            float n0 = tanh_(x0 + rg0*hh0), n1 = tanh_(x1 + rg1*hh1);
            float o0 = (1.f-z0)*hp0 + z0*n0;
            float o1 = (1.f-z1)*hp1 + z1*n1;
            hd[(size_t)(r0+rl)*UU + u0+ul]   = o0;
            hd[(size_t)(r0+rl+1)*UU + u0+ul] = o1;
            eob[((size_t)(r0+rl)*TT + t)*UU + u0+ul]   = __float2bfloat16_rn(o0);
            eob[((size_t)(r0+rl+1)*TT + t)*UU + u0+ul] = __float2bfloat16_rn(o1);
        }

        __threadfence();
        __syncthreads();
        if (tx == 0){
            atomicAdd(&g_es[gid], 1u);
            unsigned tgt = 8u*(unsigned)(t+1);
            while (*((volatile unsigned*)&g_es[gid]) < tgt) { }
        }
        __syncthreads();
    }
}

// ---------------- enc_proj GEMM: 8x2 register tile (measured 480us) ----------------
__global__ __launch_bounds__(256) void k_proj(const float* __restrict__ W1){
    const int cid = blockIdx.x;                 // 8064
    const int n = cid / 2688, rem = cid % 2688;
    const int r0 = (rem >> 2) * 64, j0 = (rem & 3) * 64;
    const int tx = threadIdx.x;
    const int ty = tx >> 5;
    const int tix = tx & 31;

    __shared__ __align__(16) float sa[64][66];
    __shared__ __align__(16) float sb[64][66];

    const __nv_bfloat16* A = &g_eoh[n][0][0];
    const float* Bw = W1 + (size_t)n*UU*UU;

    ull acc[4][2];
    #pragma unroll
    for (int rp=0;rp<4;++rp){ acc[rp][0]=pack2(0.f,0.f); acc[rp][1]=pack2(0.f,0.f); }

    for (int kc=0;kc<4;++kc){
        {
            int idx = tx;
            #pragma unroll
            for (int i=0;i<16;++i, idx+=256){
                int row = idx>>6, k = idx&63;
                sa[k][row] = __bfloat162float(A[(size_t)(r0+row)*UU + kc*64 + k]);
            }
            idx = tx;
            #pragma unroll
            for (int i=0;i<16;++i, idx+=256){
                int k = idx>>6, col = idx&63;
                sb[k][col] = Bw[(size_t)(kc*64+k)*UU + j0 + col];
            }
        }
        __syncthreads();
        #pragma unroll 2
        for (int k=0;k<64;++k){
            const float* ar = &sa[k][ty*8];
            ull a0 = *(const ull*)(ar+0);
            ull a1 = *(const ull*)(ar+2);
            ull a2 = *(const ull*)(ar+4);
            ull a3 = *(const ull*)(ar+6);
            ull bp = *(const ull*)&sb[k][tix*2];
            float b0,b1; unpack2(bp,b0,b1);
            ull w0 = pack2(b0,b0), w1 = pack2(b1,b1);
            fma2(acc[0][0],a0,w0); fma2(acc[0][1],a0,w1);
            fma2(acc[1][0],a1,w0); fma2(acc[1][1],a1,w1);
            fma2(acc[2][0],a2,w0); fma2(acc[2][1],a2,w1);
            fma2(acc[3][0],a3,w0); fma2(acc[3][1],a3,w1);
        }
        __syncthreads();
    }
    __nv_bfloat16* C = &g_pjh[n][0][0];
    #pragma unroll
    for (int rp=0;rp<4;++rp){
        float r0c0, r1c0, r0c1, r1c1;
        unpack2(acc[rp][0], r0c0, r1c0);
        unpack2(acc[rp][1], r0c1, r1c1);
        int rowA = r0 + ty*8 + 2*rp;
        float2 f0; f0.x = r0c0; f0.y = r0c1;
        float2 f1; f1.x = r1c0; f1.y = r1c1;
        *(__nv_bfloat162*)&C[(size_t)rowA*UU + j0 + tix*2]     = __float22bfloat162_rn(f0);
        *(__nv_bfloat162*)&C[(size_t)(rowA+1)*UU + j0 + tix*2] = __float22bfloat162_rn(f1);
    }
}

// ================= decoder: 3 kernels per step =================

// ---- A: K-split GRU GEMM (grid 256, K=128/CTA, 2 CTAs/SM) + fused fan-in pointwise ----
#define A2_SMEM ((12288 + 8448)*4)
__global__ __launch_bounds__(256,2) void k_dA(const float* __restrict__ dW, const float* __restrict__ dU,
        const float* __restrict__ db, const float* __restrict__ dinp, int s){
    extern __shared__ float sm[];
    float* swD = sm;              // 128 k x 96 cols
    float* sh  = sm + 12288;      // 128 k x 66 (64 rows + pad)
    __shared__ int s_last;

    const int cid = blockIdx.x;
    const int tx = threadIdx.x;
    const int ul = tx & 31, grp = tx >> 5;
    const int kt2 = cid >> 5, rem = cid & 31;
    const int kt = kt2 >> 1, khalf = kt2 & 1;
    const int r0 = (rem >> 3)*64, u0 = (rem & 7)*32;

    const float* hsrc = &g_hd2[s & 1][0][0];
    float*       hdst = &g_hd2[(s+1) & 1][0][0];

    // stage weights: float4, 3072 ld128 total
    const float* wb = ((kt < 3) ? (dW + (size_t)kt*256*U3) : dU) + (size_t)khalf*128*U3;
    for (int idx = tx; idx < 3072; idx += 256){
        int k = idx/24, c4 = idx - k*24;
        int col = c4*4, g = col >> 5, cc = col & 31;
        *(float4*)&swD[k*96 + col] = *(const float4*)(wb + (size_t)k*U3 + g*256 + u0 + cc);
    }
    // stage activations
    const float* src; int stride, koff;
    if (kt < 3){ src = &g_c[0][0]; stride = U3; koff = kt*256 + khalf*128; }
    else       { src = hsrc;       stride = UU; koff = khalf*128; }
    #pragma unroll 8
    for (int i = 0; i < 32; ++i){
        int idx = tx + i*256;
        int row = idx >> 7, k = idx & 127;
        sh[k*66 + row] = src[(size_t)(r0+row)*stride + koff + k];
    }
    __syncthreads();

    ull az[4], ar[4], an[4];
    #pragma unroll
    for (int j=0;j<4;++j){ az[j]=pack2(0.f,0.f); ar[j]=pack2(0.f,0.f); an[j]=pack2(0.f,0.f); }
    #pragma unroll 2
    for (int k = 0; k < 128; ++k){
        const float* wrow = swD + k*96;
        float wza = wrow[ul], wra = wrow[32+ul], wna = wrow[64+ul];
        ull wz = pack2(wza,wza), wr = pack2(wra,wra), wn = pack2(wna,wna);
        const float* hrow = sh + k*66 + grp*8;
        #pragma unroll
        for (int j=0;j<4;++j){
            ull h2 = *(const ull*)&hrow[2*j];
            fma2(az[j],h2,wz); fma2(ar[j],h2,wr); fma2(an[j],h2,wn);
        }
    }
    float* dp = &g_dp2[kt2][0][0];
    #pragma unroll
    for (int j=0;j<4;++j){
        int rl = grp*8 + 2*j; float a0,a1;
        unpack2(az[j],a0,a1); dp[(r0+rl)*U3 + u0+ul] = a0;       dp[(r0+rl+1)*U3 + u0+ul] = a1;
        unpack2(ar[j],a0,a1); dp[(r0+rl)*U3 + 256 + u0+ul] = a0; dp[(r0+rl+1)*U3 + 256 + u0+ul] = a1;
        unpack2(an[j],a0,a1); dp[(r0+rl)*U3 + 512 + u0+ul] = a0; dp[(r0+rl+1)*U3 + 512 + u0+ul] = a1;
    }

    // fan-in: last of the 8 K-chunk CTAs for this (row,col) block does the pointwise GRU
    __threadfence();
    __syncthreads();
    if (tx == 0){
        unsigned old = atomicAdd(&g_dcnt[rem], 1u);
        s_last = (old == (unsigned)(8*s + 7)) ? 1 : 0;
    }
    __syncthreads();
    if (s_last){
        __threadfence();
        const float* dWl = dW + (size_t)768*U3;
        #pragma unroll
        for (int e = tx; e < 2048; e += 256){
            int rr = r0 + (e >> 5), u = u0 + (e & 31);
            float d  = dinp[rr*HH + s];
            float zp = db[u]     + d*dWl[u];
            float rp = db[256+u] + d*dWl[256+u];
            float nx = db[512+u] + d*dWl[512+u];
            #pragma unroll
            for (int q = 0; q < 8; ++q){
                zp += g_dp2[q][rr][u];
                rp += g_dp2[q][rr][256+u];
            }
            #pragma unroll
            for (int q = 0; q < 6; ++q) nx += g_dp2[q][rr][512+u];
            float nh = g_dp2[6][rr][512+u] + g_dp2[7][rr][512+u];
            float z = sigm(zp), rg = sigm(rp);
            float nn = tanh_(nx + rg*nh);
            float hp = hsrc[rr*UU + u];
            hdst[rr*UU + u] = (1.f-z)*hp + z*nn;
        }
    }
}

// ---- C: q = h @ att_W2, K-split (grid 192), partial outputs ----
#define C2_SMEM ((4096 + 8448)*4)
__global__ __launch_bounds__(256,2) void k_dC(const float* __restrict__ W2, int s){
    extern __shared__ float sm[];
    float* sw2 = sm;              // 128 k x 32
    float* sh  = sm + 4096;       // 128 k x 66

    const int cid = blockIdx.x;   // 192
    const int tx = threadIdx.x;
    const int ul = tx & 31, grp = tx >> 5;
    const int n2 = cid / 64;
    const int r  = cid % 64;
    const int khalf = r >> 5;
    const int rm = r & 31;
    const int rr0 = (rm >> 3)*64, v0 = (rm & 7)*32;

    const float* hq = &g_hd2[(s+1) & 1][0][0];

    for (int idx = tx; idx < 1024; idx += 256){
        int k = idx >> 3, c4 = idx & 7;
        *(float4*)&sw2[k*32 + c4*4] =
            *(const float4*)(W2 + (size_t)n2*UU*UU + (size_t)(khalf*128 + k)*UU + v0 + c4*4);
    }
    #pragma unroll 8
    for (int i = 0; i < 32; ++i){
        int idx = tx + i*256;
        int row = idx >> 7, k = idx & 127;
        sh[k*66 + row] = hq[(size_t)(rr0+row)*UU + khalf*128 + k];
    }
    __syncthreads();

    ull ac[4];
    #pragma unroll
    for (int j=0;j<4;++j) ac[j] = pack2(0.f,0.f);
    #pragma unroll 2
    for (int k = 0; k < 128; ++k){
        float w = sw2[k*32 + ul];
        ull w2 = pack2(w,w);
        const float* hrow = sh + k*66 + grp*8;
        #pragma unroll
        for (int j=0;j<4;++j) fma2(ac[j], *(const ull*)&hrow[2*j], w2);
    }
    #pragma unroll
    for (int j=0;j<4;++j){
        int rl = grp*8 + 2*j; float a0,a1; unpack2(ac[j],a0,a1);
        g_q2[khalf][n2][rr0+rl][v0+ul]   = a0;
        g_q2[khalf][n2][rr0+rl+1][v0+ul] = a1;
    }
}

// ---- D: attention (grid 768); q = sum of 2 partials; eo __ldcs keeps pj L2-resident ----
__global__ __launch_bounds__(256) void k_dD(const float* __restrict__ av){
    __shared__ __align__(16) float q_s[256], v_s[256];
    __shared__ float sc_s[176];
    __shared__ __align__(16) float sred[1024];

    const int tx = threadIdx.x, lane = tx & 31, wid = tx >> 5;
    const int n3 = blockIdx.x >> 8, b = blockIdx.x & 255;

    q_s[tx] = g_q2[0][n3][b][tx] + g_q2[1][n3][b][tx];
    v_s[tx] = av[n3*UU + tx];
    __syncthreads();

    const __nv_bfloat16* pj = &g_pjh[n3][0][0] + (size_t)b*TT*UU;
    #pragma unroll 3
    for (int ii = 0; ii < 21; ++ii){
        int t = wid*21 + ii;
        const uint2* row = (const uint2*)(pj + (size_t)t*UU);
        float acc = 0.f;
        #pragma unroll
        for (int j2 = 0; j2 < 2; ++j2){
            int v = j2*128 + 4*lane;
            uint2 pk = row[j2*32 + lane];
            float4 qv = *(const float4*)&q_s[v];
            float4 vv = *(const float4*)&v_s[v];
            acc += tanha(blo(pk.x) + qv.x) * vv.x;
            acc += tanha(bhi(pk.x) + qv.y) * vv.y;
            acc += tanha(blo(pk.y) + qv.z) * vv.z;
            acc += tanha(bhi(pk.y) + qv.w) * vv.w;
        }
        #pragma unroll
        for (int o = 16; o > 0; o >>= 1) acc += __shfl_xor_sync(0xffffffffu, acc, o);
        if (lane == 0) sc_s[t] = acc;
    }
    __syncthreads();
    if (wid == 0){
        float m = -1e30f;
        for (int t = lane; t < TT; t += 32) m = fmaxf(m, sc_s[t]);
        #pragma unroll
        for (int o = 16; o > 0; o >>= 1) m = fmaxf(m, __shfl_xor_sync(0xffffffffu, m, o));
        float ss = 0.f;
        for (int t = lane; t < TT; t += 32){ float e2 = __expf(sc_s[t]-m); sc_s[t] = e2; ss += e2; }
        #pragma unroll
        for (int o = 16; o > 0; o >>= 1) ss += __shfl_xor_sync(0xffffffffu, ss, o);
        float inv = __fdividef(1.f, ss);
        for (int t = lane; t < TT; t += 32) sc_s[t] *= inv;
    }
    __syncthreads();
    {
        int tg = tx >> 6, uq = tx & 63;
        const __nv_bfloat16* eob = &g_eoh[n3][0][0] + (size_t)b*TT*UU;
        float4 a = make_float4(0.f,0.f,0.f,0.f);
        #pragma unroll 6
        for (int i = 0; i < 42; ++i){
            int t = tg + 4*i;
            uint2 e = __ldcs((const uint2*)(eob + (size_t)t*UU) + uq);
            float w = sc_s[t];
            a.x += w*blo(e.x); a.y += w*bhi(e.x);
            a.z += w*blo(e.y); a.w += w*bhi(e.y);
        }
        ((float4*)sred)[tg*64 + uq] = a;
    }
    __syncthreads();
    {
        int uq = tx >> 2, comp = tx & 3;
        float sum = sred[(0*64 + uq)*4 + comp] + sred[(1*64 + uq)*4 + comp]
                  + sred[(2*64 + uq)*4 + comp] + sred[(3*64 + uq)*4 + comp];
        g_c[b][n3*UU + tx] = sum;
    }
}

// ---------------- head part 1 ----------------
__global__ __launch_bounds__(256) void k_h1(const float* __restrict__ W1, const float* __restrict__ b1){
    const int rem = blockIdx.x;          // 32
    const int r0 = (rem>>2)*32, j0 = (rem&3)*64;
    const int tx = threadIdx.x, ul = tx&63, grp = tx>>6;
    __shared__ __align__(16) float sh[256][34];
    ull acc[4];
    #pragma unroll
    for (int j=0;j<4;++j) acc[j]=pack2(0.f,0.f);
    for (int cc=0;cc<4;++cc){
        const float* src = (cc==0) ? &g_hd2[0][0][0] : (&g_c[0][0] + (cc-1)*256);
        int stride = (cc==0) ? UU : U3;
        __syncthreads();
        #pragma unroll 8
        for (int i=0;i<32;++i) sh[tx][i] = src[(r0+i)*stride + tx];
        __syncthreads();
        const float* wp = W1 + cc*256*UU + j0 + ul;
        #pragma unroll 2
        for (int k=0;k<256;++k){
            float w = wp[k*UU];
            ull w2 = pack2(w,w);
            #pragma unroll
            for (int j=0;j<4;++j) fma2(acc[j], *(const ull*)&sh[k][(grp*4+j)*2], w2);
        }
    }
    float bb = b1[j0+ul];
    #pragma unroll
    for (int j=0;j<4;++j){
        int rl=(grp*4+j)*2; float a0,a1; unpack2(acc[j],a0,a1);
        g_s1[r0+rl][j0+ul]   = a0+bb;
        g_s1[r0+rl+1][j0+ul] = a1+bb;
    }
}

// ---------------- head part 2 ----------------
__global__ __launch_bounds__(256) void k_h2(const float* __restrict__ ef, const float* __restrict__ eW,
        const float* __restrict__ eb, const float* __restrict__ W1, const float* __restrict__ w2v,
        const float* __restrict__ b2, float* __restrict__ out){
    const int b = blockIdx.x, tx = threadIdx.x, lane = tx&31, wid = tx>>5;
    __shared__ __align__(16) float se[256][26];
    __shared__ float sf[384];
    __shared__ float prt[8][24];
    sf[tx < 384 ? tx : 0] = ef[b*384 + (tx < 384 ? tx : 0)];
    if (tx < 128) sf[256+tx] = ef[b*384 + 256 + tx];
    __syncthreads();
    float wk[16];
    #pragma unroll
    for (int k=0;k<16;++k) wk[k] = eW[k*UU + tx];
    float ebv = eb[tx];
    #pragma unroll
    for (int h=0;h<24;++h){
        float a = ebv;
        #pragma unroll
        for (int k=0;k<16;++k) a += sf[h*16+k]*wk[k];
        se[tx][h] = fmaxf(a, 0.f);
    }
    __syncthreads();
    ull y2[12];
    #pragma unroll
    for (int p=0;p<12;++p) y2[p]=pack2(0.f,0.f);
    const float* wp = W1 + 1024*UU + tx;
    #pragma unroll 2
    for (int k=0;k<256;++k){
        float w = wp[k*UU];
        ull w2 = pack2(w,w);
        #pragma unroll
        for (int p=0;p<12;++p) fma2(y2[p], *(const ull*)&se[k][2*p], w2);
    }
    float sp = g_s1[b][tx];
    float wo = w2v[tx];
    float ct[24];
    #pragma unroll
    for (int p=0;p<12;++p){
        float a0,a1; unpack2(y2[p],a0,a1);
        ct[2*p]   = fmaxf(sp+a0, 0.f)*wo;
        ct[2*p+1] = fmaxf(sp+a1, 0.f)*wo;
    }
    #pragma unroll
    for (int h=0;h<24;++h){
        #pragma unroll
        for (int o=16;o>0;o>>=1) ct[h] += __shfl_xor_sync(0xffffffffu, ct[h], o);
    }
    if (lane==0){
        #pragma unroll
        for (int h=0;h<24;++h) prt[wid][h] = ct[h];
    }
    __syncthreads();
    if (tx < 24){
        float s2 = b2[0];
        #pragma unroll
        for (int w=0;w<8;++w) s2 += prt[w][tx];
        out[b*HH + tx] = s2;
    }
}

extern "C" void kernel_launch(void* const* d_in, const int* in_sizes, int n_in,
                              void* d_out, int out_size){
    const float* enc_in = (const float*)d_in[0];
    const float* dec_in = (const float*)d_in[1];
    const float* ext_f  = (const float*)d_in[2];
    const float* enc_W  = (const float*)d_in[3];
    const float* enc_U  = (const float*)d_in[4];
    const float* enc_b  = (const float*)d_in[5];
    const float* att_W1 = (const float*)d_in[6];
    const float* att_W2 = (const float*)d_in[7];
    const float* att_v  = (const float*)d_in[8];
    const float* dec_W  = (const float*)d_in[9];
    const float* dec_U  = (const float*)d_in[10];
    const float* dec_b  = (const float*)d_in[11];
    const float* ext_W  = (const float*)d_in[12];
    const float* ext_b  = (const float*)d_in[13];
    const float* out1_W = (const float*)d_in[14];
    const float* out1_b = (const float*)d_in[15];
    const float* out2_W = (const float*)d_in[16];
    const float* out2_b = (const float*)d_in[17];
    float* out = (float*)d_out;

    const int enc_smem = E_TOT * 4;   // 186624 B
    cudaFuncSetAttribute(k_enc, cudaFuncAttributeMaxDynamicSharedMemorySize, enc_smem);
    cudaFuncSetAttribute(k_dA, cudaFuncAttributeMaxDynamicSharedMemorySize, A2_SMEM);
    cudaFuncSetAttribute(k_dC, cudaFuncAttributeMaxDynamicSharedMemorySize, C2_SMEM);

    k_init<<<768,  256>>>();
    k_enc <<<96,   256, enc_smem>>>(enc_in, enc_W, enc_U, enc_b);
    k_proj<<<8064, 256>>>(att_W1);

    for (int s = 0; s < HH; ++s){
        k_dA<<<256, 256, A2_SMEM>>>(dec_W, dec_U, dec_b, dec_in, s);
        k_dC<<<192, 256, C2_SMEM>>>(att_W2, s);
        k_dD<<<768, 256>>>(att_v);
    }

    k_h1<<<32,  256>>>(out1_W, out1_b);
    k_h2<<<256, 256>>>(ext_f, ext_W, ext_b, out1_W, out2_W, out2_b, out);
}

// round 11
// speedup vs baseline: 1.0022x; 1.0022x over previous
#include <cuda_runtime.h>
#include <cuda_bf16.h>

#define NE 3
#define BB 256
#define TT 168
#define DE 32
#define UU 256
#define U3 768
#define HH 24
#define BT (BB*TT)

typedef unsigned long long ull;

__device__ __forceinline__ ull pack2(float lo, float hi){ ull r; asm("mov.b64 %0,{%1,%2};":"=l"(r):"f"(lo),"f"(hi)); return r; }
__device__ __forceinline__ void unpack2(ull v, float&lo, float&hi){ asm("mov.b64 {%0,%1},%2;":"=f"(lo),"=f"(hi):"l"(v)); }
__device__ __forceinline__ void fma2(ull&d, ull a, ull b){ asm("fma.rn.f32x2 %0,%1,%2,%0;":"+l"(d):"l"(a),"l"(b)); }

__device__ __forceinline__ float sigm(float x){ return __fdividef(1.f, 1.f + __expf(-x)); }
__device__ __forceinline__ float tanh_(float x){
    float e = __expf(-2.f*fabsf(x));
    float t = __fdividef(1.f-e, 1.f+e);
    return copysignf(t,x);
}
__device__ __forceinline__ float tanha(float x){ float y; asm("tanh.approx.f32 %0,%1;":"=f"(y):"f"(x)); return y; }
__device__ __forceinline__ float blo(unsigned pk){ return __uint_as_float(pk << 16); }
__device__ __forceinline__ float bhi(unsigned pk){ return __uint_as_float(pk & 0xffff0000u); }

// ---------------- device scratch ----------------
__device__ __align__(16) __nv_bfloat16 g_eoh[NE][BT][UU]; // enc_out bf16
__device__ __align__(16) __nv_bfloat16 g_pjh[NE][BT][UU]; // enc_proj bf16
__device__ __align__(16) float g_h[2][NE][BB][UU];        // encoder hidden ping-pong
__device__ __align__(16) float g_hd[BB][UU];
__device__ __align__(16) float g_c[BB][U3];
__device__ __align__(16) float g_q[NE][BB][UU];
__device__ __align__(16) float g_dp[4][BB][U3];
__device__ __align__(16) float g_s1[BB][UU];
__device__ unsigned g_es[12];

__global__ void k_init(){
    int i = blockIdx.x*256 + threadIdx.x;   // 768*256 = 196608
    ((float*)g_h)[i] = 0.f;                  // zeros buffer 0 exactly (NE*BB*UU)
    if (i < BB*UU) ((float*)g_hd)[i] = 0.f;
    if (i < BB*U3) ((float*)g_c)[i]  = 0.f;
    if (i < 12)    g_es[i] = 0u;
}

// ---------------- encoder: SMEM-resident weights, 8-CTA group sync (R9, passing) ----------------
#define E_SWU 0
#define E_SWX 24576
#define E_SH  27648
#define E_SXI 44544
#define E_TOT 46656

__global__ __launch_bounds__(256,1) void k_enc(const float* __restrict__ X, const float* __restrict__ W,
                                               const float* __restrict__ Uw, const float* __restrict__ bv){
    extern __shared__ float sm[];
    float* swU = sm + E_SWU;
    float* swX = sm + E_SWX;
    float* sh  = sm + E_SH;
    float* sxi = sm + E_SXI;

    const int cid = blockIdx.x;
    const int n = cid >> 5, rem = cid & 31;
    const int r0 = (rem >> 3) * 64, u0 = (rem & 7) * 32;
    const int gid = n*4 + (rem >> 3);
    const int tx = threadIdx.x, ul = tx & 31, grp = tx >> 5;

    for (int idx = tx; idx < 24576; idx += 256){
        int k = idx / 96, c = idx % 96;
        int g = c >> 5, cc = c & 31;
        swU[idx] = Uw[(size_t)n*UU*U3 + (size_t)k*U3 + g*256 + u0 + cc];
    }
    for (int idx = tx; idx < 3072; idx += 256){
        int k = idx / 96, c = idx % 96;
        int g = c >> 5, cc = c & 31;
        swX[idx] = W[(size_t)n*DE*U3 + (size_t)k*U3 + g*256 + u0 + cc];
    }
    const float bz = bv[n*U3 + u0+ul];
    const float br = bv[n*U3 + 256 + u0+ul];
    const float bn = bv[n*U3 + 512 + u0+ul];
    __syncthreads();

    __nv_bfloat16* eob = &g_eoh[n][0][0];

    for (int t = 0; t < TT; ++t){
        const float* hs = &g_h[t&1][n][0][0];
        #pragma unroll 8
        for (int i = 0; i < 64; ++i) sh[tx*66 + i] = __ldcg(hs + (size_t)(r0+i)*UU + tx);
        {
            int idx = tx;
            #pragma unroll
            for (int i = 0; i < 8; ++i, idx += 256){
                int row = idx >> 5, col = idx & 31;
                sxi[col*66 + row] = X[(((size_t)n*BB + r0+row)*TT + t)*DE + col];
            }
        }
        __syncthreads();

        ull az[4], ar[4], ax[4], ah[4];
        #pragma unroll
        for (int j=0;j<4;++j){ az[j]=pack2(bz,bz); ar[j]=pack2(br,br); ax[j]=pack2(bn,bn); ah[j]=pack2(0.f,0.f); }

        #pragma unroll 4
        for (int k = 0; k < 256; ++k){
            const float* wrow = swU + k*96;
            float wza = wrow[ul], wra = wrow[32+ul], wna = wrow[64+ul];
            ull wz = pack2(wza,wza), wr = pack2(wra,wra), wn = pack2(wna,wna);
            const float* hrow = sh + k*66 + grp*8;
            #pragma unroll
            for (int j=0;j<4;++j){
                ull h2 = *(const ull*)&hrow[2*j];
                fma2(az[j],h2,wz); fma2(ar[j],h2,wr); fma2(ah[j],h2,wn);
            }
        }
        #pragma unroll 4
        for (int k = 0; k < 32; ++k){
            const float* wrow = swX + k*96;
            float wza = wrow[ul], wra = wrow[32+ul], wna = wrow[64+ul];
            ull wz = pack2(wza,wza), wr = pack2(wra,wra), wn = pack2(wna,wna);
            const float* xrow = sxi + k*66 + grp*8;
            #pragma unroll
            for (int j=0;j<4;++j){
                ull x2 = *(const ull*)&xrow[2*j];
                fma2(az[j],x2,wz); fma2(ar[j],x2,wr); fma2(ax[j],x2,wn);
            }
        }

        float* hd = &g_h[(t+1)&1][n][0][0];
        #pragma unroll
        for (int j=0;j<4;++j){
            int rl = grp*8 + 2*j;
            float z0,z1,rg0,rg1,x0,x1,hh0,hh1;
            unpack2(az[j],z0,z1); unpack2(ar[j],rg0,rg1); unpack2(ax[j],x0,x1); unpack2(ah[j],hh0,hh1);
            float hp0 = sh[(u0+ul)*66 + rl];
            float hp1 = sh[(u0+ul)*66 + rl + 1];
            z0=sigm(z0); z1=sigm(z1); rg0=sigm(rg0); rg1=sigm(rg1);
            float n0 = tanh_(x0 + rg0*hh0), n1 = tanh_(x1 + rg1*hh1);
            float o0 = (1.f-z0)*hp0 + z0*n0;
            float o1 = (1.f-z1)*hp1 + z1*n1;
            hd[(size_t)(r0+rl)*UU + u0+ul]   = o0;
            hd[(size_t)(r0+rl+1)*UU + u0+ul] = o1;
            eob[((size_t)(r0+rl)*TT + t)*UU + u0+ul]   = __float2bfloat16_rn(o0);
            eob[((size_t)(r0+rl+1)*TT + t)*UU + u0+ul] = __float2bfloat16_rn(o1);
        }

        __threadfence();
        __syncthreads();
        if (tx == 0){
            atomicAdd(&g_es[gid], 1u);
            unsigned tgt = 8u*(unsigned)(t+1);
            while (*((volatile unsigned*)&g_es[gid]) < tgt) { }
        }
        __syncthreads();
    }
}

// ---------------- enc_proj GEMM: 8x2 register tile (measured 480us) ----------------
__global__ __launch_bounds__(256) void k_proj(const float* __restrict__ W1){
    const int cid = blockIdx.x;                 // 8064
    const int n = cid / 2688, rem = cid % 2688;
    const int r0 = (rem >> 2) * 64, j0 = (rem & 3) * 64;
    const int tx = threadIdx.x;
    const int ty = tx >> 5;
    const int tix = tx & 31;

    __shared__ __align__(16) float sa[64][66];
    __shared__ __align__(16) float sb[64][66];

    const __nv_bfloat16* A = &g_eoh[n][0][0];
    const float* Bw = W1 + (size_t)n*UU*UU;

    ull acc[4][2];
    #pragma unroll
    for (int rp=0;rp<4;++rp){ acc[rp][0]=pack2(0.f,0.f); acc[rp][1]=pack2(0.f,0.f); }

    for (int kc=0;kc<4;++kc){
        {
            int idx = tx;
            #pragma unroll
            for (int i=0;i<16;++i, idx+=256){
                int row = idx>>6, k = idx&63;
                sa[k][row] = __bfloat162float(A[(size_t)(r0+row)*UU + kc*64 + k]);
            }
            idx = tx;
            #pragma unroll
            for (int i=0;i<16;++i, idx+=256){
                int k = idx>>6, col = idx&63;
                sb[k][col] = Bw[(size_t)(kc*64+k)*UU + j0 + col];
            }
        }
        __syncthreads();
        #pragma unroll 2
        for (int k=0;k<64;++k){
            const float* ar = &sa[k][ty*8];
            ull a0 = *(const ull*)(ar+0);
            ull a1 = *(const ull*)(ar+2);
            ull a2 = *(const ull*)(ar+4);
            ull a3 = *(const ull*)(ar+6);
            ull bp = *(const ull*)&sb[k][tix*2];
            float b0,b1; unpack2(bp,b0,b1);
            ull w0 = pack2(b0,b0), w1 = pack2(b1,b1);
            fma2(acc[0][0],a0,w0); fma2(acc[0][1],a0,w1);
            fma2(acc[1][0],a1,w0); fma2(acc[1][1],a1,w1);
            fma2(acc[2][0],a2,w0); fma2(acc[2][1],a2,w1);
            fma2(acc[3][0],a3,w0); fma2(acc[3][1],a3,w1);
        }
        __syncthreads();
    }
    __nv_bfloat16* C = &g_pjh[n][0][0];
    #pragma unroll
    for (int rp=0;rp<4;++rp){
        float r0c0, r1c0, r0c1, r1c1;
        unpack2(acc[rp][0], r0c0, r1c0);
        unpack2(acc[rp][1], r0c1, r1c1);
        int rowA = r0 + ty*8 + 2*rp;
        float2 f0; f0.x = r0c0; f0.y = r0c1;
        float2 f1; f1.x = r1c0; f1.y = r1c1;
        *(__nv_bfloat162*)&C[(size_t)rowA*UU + j0 + tix*2]     = __float22bfloat162_rn(f0);
        *(__nv_bfloat162*)&C[(size_t)(rowA+1)*UU + j0 + tix*2] = __float22bfloat162_rn(f1);
    }
}

// ================= decoder: 4 kernels per step (R9 structure) =================

// ---- A: K-split GRU GEMM (grid 128), float4 weight staging ----
#define A_SMEM ((24576+16896)*4)
__global__ __launch_bounds__(256,1) void k_dA(const float* __restrict__ dW, const float* __restrict__ dU){
    extern __shared__ float sm[];
    float* swD = sm;
    float* sh  = sm + 24576;

    const int cid = blockIdx.x;
    const int tx = threadIdx.x;
    const int ul = tx & 31, grp = tx >> 5;
    const int kt  = cid >> 5;
    const int rem = cid & 31;
    const int r0  = (rem >> 3) * 64, u0 = (rem & 7) * 32;

    const float* wb = (kt < 3) ? (dW + (size_t)kt*256*U3) : dU;
    for (int idx = tx; idx < 6144; idx += 256){
        int k = idx / 24, c4 = idx - k*24;
        int col = c4*4, g = col >> 5, cc = col & 31;
        *(float4*)&swD[k*96 + col] = *(const float4*)(wb + (size_t)k*U3 + g*256 + u0 + cc);
    }
    const float* src; int stride, koff;
    if (kt < 3){ src = &g_c[0][0]; stride = U3; koff = kt*256; }
    else       { src = &g_hd[0][0]; stride = UU; koff = 0; }
    #pragma unroll 8
    for (int i = 0; i < 64; ++i) sh[tx*66 + i] = src[(size_t)(r0+i)*stride + koff + tx];
    __syncthreads();

    ull az[4], ar[4], an[4];
    #pragma unroll
    for (int j=0;j<4;++j){ az[j]=pack2(0.f,0.f); ar[j]=pack2(0.f,0.f); an[j]=pack2(0.f,0.f); }
    #pragma unroll 2
    for (int k = 0; k < 256; ++k){
        const float* wrow = swD + k*96;
        float wza = wrow[ul], wra = wrow[32+ul], wna = wrow[64+ul];
        ull wz = pack2(wza,wza), wr = pack2(wra,wra), wn = pack2(wna,wna);
        const float* hrow = sh + k*66 + grp*8;
        #pragma unroll
        for (int j=0;j<4;++j){
            ull h2 = *(const ull*)&hrow[2*j];
            fma2(az[j],h2,wz); fma2(ar[j],h2,wr); fma2(an[j],h2,wn);
        }
    }
    float* dp = &g_dp[kt][0][0];
    #pragma unroll
    for (int j=0;j<4;++j){
        int rl = grp*8 + 2*j; float a0,a1;
        unpack2(az[j],a0,a1); dp[(r0+rl)*U3 + u0+ul] = a0;       dp[(r0+rl+1)*U3 + u0+ul] = a1;
        unpack2(ar[j],a0,a1); dp[(r0+rl)*U3 + 256 + u0+ul] = a0; dp[(r0+rl+1)*U3 + 256 + u0+ul] = a1;
        unpack2(an[j],a0,a1); dp[(r0+rl)*U3 + 512 + u0+ul] = a0; dp[(r0+rl+1)*U3 + 512 + u0+ul] = a1;
    }
}

// ---- B: reduce partials + pointwise GRU (grid 256) ----
__global__ __launch_bounds__(256) void k_dB(const float* __restrict__ dW, const float* __restrict__ db,
                                            const float* __restrict__ dinp, int s){
    int r = blockIdx.x, u = threadIdx.x;
    float d  = dinp[r*HH + s];
    float zp = db[u]     + d*dW[(size_t)768*U3 + u];
    float rp = db[256+u] + d*dW[(size_t)768*U3 + 256+u];
    float nx = db[512+u] + d*dW[(size_t)768*U3 + 512+u];
    float nh = g_dp[3][r][512+u];
    zp += g_dp[0][r][u] + g_dp[1][r][u] + g_dp[2][r][u] + g_dp[3][r][u];
    rp += g_dp[0][r][256+u] + g_dp[1][r][256+u] + g_dp[2][r][256+u] + g_dp[3][r][256+u];
    nx += g_dp[0][r][512+u] + g_dp[1][r][512+u] + g_dp[2][r][512+u];
    float z = sigm(zp), rg = sigm(rp);
    float nn = tanh_(nx + rg*nh);
    float hp = g_hd[r][u];
    g_hd[r][u] = (1.f-z)*hp + z*nn;
}

// ---- C: q = h @ att_W2 (grid 96), float4 weight staging ----
#define C_SMEM ((8192+16896)*4)
__global__ __launch_bounds__(256,1) void k_dC(const float* __restrict__ W2){
    extern __shared__ float sm[];
    float* sw2 = sm;
    float* sh  = sm + 8192;

    const int cid = blockIdx.x;
    const int tx = threadIdx.x;
    const int ul = tx & 31, grp = tx >> 5;
    const int n2 = cid >> 5;
    const int rm = cid & 31;
    const int rr0 = (rm >> 3) * 64, v0 = (rm & 7) * 32;

    for (int idx = tx; idx < 2048; idx += 256){
        int k = idx >> 3, c4 = idx & 7;
        *(float4*)&sw2[k*32 + c4*4] =
            *(const float4*)(W2 + (size_t)n2*UU*UU + (size_t)k*UU + v0 + c4*4);
    }
    #pragma unroll 8
    for (int i = 0; i < 64; ++i) sh[tx*66 + i] = g_hd[rr0+i][tx];
    __syncthreads();

    ull ac[4];
    #pragma unroll
    for (int j=0;j<4;++j) ac[j] = pack2(0.f,0.f);
    #pragma unroll 2
    for (int k = 0; k < 256; ++k){
        float w = sw2[k*32 + ul];
        ull w2 = pack2(w,w);
        const float* hrow = sh + k*66 + grp*8;
        #pragma unroll
        for (int j=0;j<4;++j) fma2(ac[j], *(const ull*)&hrow[2*j], w2);
    }
    #pragma unroll
    for (int j=0;j<4;++j){
        int rl = grp*8 + 2*j; float a0,a1; unpack2(ac[j],a0,a1);
        g_q[n2][rr0+rl][v0+ul]   = a0;
        g_q[n2][rr0+rl+1][v0+ul] = a1;
    }
}

// ---- D: attention (grid 768), high-MLP uint4 streams ----
__global__ __launch_bounds__(256) void k_dD(const float* __restrict__ av){
    __shared__ __align__(16) float q_s[256], v_s[256];
    __shared__ float sc_s[176];
    __shared__ __align__(16) float sred[2048];   // 8 t-groups x 256 cols

    const int tx = threadIdx.x, lane = tx & 31, wid = tx >> 5;
    const int n3 = blockIdx.x >> 8, b = blockIdx.x & 255;

    q_s[tx] = g_q[n3][b][tx];
    v_s[tx] = av[n3*UU + tx];
    __syncthreads();

    // scores: warp per 21 rows, 1 LDG.128 per row per lane, q/v hoisted to regs
    {
        const float4 q0 = *(const float4*)&q_s[8*lane];
        const float4 q1 = *(const float4*)&q_s[8*lane+4];
        const float4 vv0 = *(const float4*)&v_s[8*lane];
        const float4 vv1 = *(const float4*)&v_s[8*lane+4];
        const uint4* pj4 = (const uint4*)(&g_pjh[n3][0][0] + (size_t)b*TT*UU);
        #pragma unroll 7
        for (int ii = 0; ii < 21; ++ii){
            int t = wid*21 + ii;
            uint4 pk = __ldcg(pj4 + (size_t)t*32 + lane);
            float acc;
            acc  = tanha(blo(pk.x) + q0.x) * vv0.x;
            acc += tanha(bhi(pk.x) + q0.y) * vv0.y;
            acc += tanha(blo(pk.y) + q0.z) * vv0.z;
            acc += tanha(bhi(pk.y) + q0.w) * vv0.w;
            acc += tanha(blo(pk.z) + q1.x) * vv1.x;
            acc += tanha(bhi(pk.z) + q1.y) * vv1.y;
            acc += tanha(blo(pk.w) + q1.z) * vv1.z;
            acc += tanha(bhi(pk.w) + q1.w) * vv1.w;
            #pragma unroll
            for (int o = 16; o > 0; o >>= 1) acc += __shfl_xor_sync(0xffffffffu, acc, o);
            if (lane == 0) sc_s[t] = acc;
        }
    }
    __syncthreads();
    if (wid == 0){
        float m = -1e30f;
        for (int t = lane; t < TT; t += 32) m = fmaxf(m, sc_s[t]);
        #pragma unroll
        for (int o = 16; o > 0; o >>= 1) m = fmaxf(m, __shfl_xor_sync(0xffffffffu, m, o));
        float ss = 0.f;
        for (int t = lane; t < TT; t += 32){ float e2 = __expf(sc_s[t]-m); sc_s[t] = e2; ss += e2; }
        #pragma unroll
        for (int o = 16; o > 0; o >>= 1) ss += __shfl_xor_sync(0xffffffffu, ss, o);
        float inv = __fdividef(1.f, ss);
        for (int t = lane; t < TT; t += 32) sc_s[t] *= inv;
    }
    __syncthreads();
    // context: 8 t-groups x 32 lanes, uint4 = 8 bf16 per thread per t
    {
        int tg = tx >> 5, uq = tx & 31;
        const uint4* eo4 = (const uint4*)(&g_eoh[n3][0][0] + (size_t)b*TT*UU);
        float4 a0 = make_float4(0.f,0.f,0.f,0.f);
        float4 a1 = make_float4(0.f,0.f,0.f,0.f);
        #pragma unroll 7
        for (int i = 0; i < 21; ++i){
            int t = tg + 8*i;
            uint4 e = __ldcs(eo4 + (size_t)t*32 + uq);
            float w = sc_s[t];
            a0.x += w*blo(e.x); a0.y += w*bhi(e.x);
            a0.z += w*blo(e.y); a0.w += w*bhi(e.y);
            a1.x += w*blo(e.z); a1.y += w*bhi(e.z);
            a1.z += w*blo(e.w); a1.w += w*bhi(e.w);
        }
        ((float4*)sred)[(tg*32 + uq)*2 + 0] = a0;
        ((float4*)sred)[(tg*32 + uq)*2 + 1] = a1;
    }
    __syncthreads();
    {
        float sum = 0.f;
        #pragma unroll
        for (int g = 0; g < 8; ++g) sum += sred[g*256 + tx];
        g_c[b][n3*UU + tx] = sum;
    }
}

// ---------------- head part 1 ----------------
__global__ __launch_bounds__(256) void k_h1(const float* __restrict__ W1, const float* __restrict__ b1){
    const int rem = blockIdx.x;          // 32
    const int r0 = (rem>>2)*32, j0 = (rem&3)*64;
    const int tx = threadIdx.x, ul = tx&63, grp = tx>>6;
    __shared__ __align__(16) float sh[256][34];
    ull acc[4];
    #pragma unroll
    for (int j=0;j<4;++j) acc[j]=pack2(0.f,0.f);
    for (int cc=0;cc<4;++cc){
        const float* src = (cc==0) ? &g_hd[0][0] : (&g_c[0][0] + (cc-1)*256);
        int stride = (cc==0) ? UU : U3;
        __syncthreads();
        #pragma unroll 8
        for (int i=0;i<32;++i) sh[tx][i] = src[(r0+i)*stride + tx];
        __syncthreads();
        const float* wp = W1 + cc*256*UU + j0 + ul;
        #pragma unroll 2
        for (int k=0;k<256;++k){
            float w = wp[k*UU];
            ull w2 = pack2(w,w);
            #pragma unroll
            for (int j=0;j<4;++j) fma2(acc[j], *(const ull*)&sh[k][(grp*4+j)*2], w2);
        }
    }
    float bb = b1[j0+ul];
    #pragma unroll
    for (int j=0;j<4;++j){
        int rl=(grp*4+j)*2; float a0,a1; unpack2(acc[j],a0,a1);
        g_s1[r0+rl][j0+ul]   = a0+bb;
        g_s1[r0+rl+1][j0+ul] = a1+bb;
    }
}

// ---------------- head part 2 ----------------
__global__ __launch_bounds__(256) void k_h2(const float* __restrict__ ef, const float* __restrict__ eW,
        const float* __restrict__ eb, const float* __restrict__ W1, const float* __restrict__ w2v,
        const float* __restrict__ b2, float* __restrict__ out){
    const int b = blockIdx.x, tx = threadIdx.x, lane = tx&31, wid = tx>>5;
    __shared__ __align__(16) float se[256][26];
    __shared__ float sf[384];
    __shared__ float prt[8][24];
    sf[tx < 384 ? tx : 0] = ef[b*384 + (tx < 384 ? tx : 0)];
    if (tx < 128) sf[256+tx] = ef[b*384 + 256 + tx];
    __syncthreads();
    float wk[16];
    #pragma unroll
    for (int k=0;k<16;++k) wk[k] = eW[k*UU + tx];
    float ebv = eb[tx];
    #pragma unroll
    for (int h=0;h<24;++h){
        float a = ebv;
        #pragma unroll
        for (int k=0;k<16;++k) a += sf[h*16+k]*wk[k];
        se[tx][h] = fmaxf(a, 0.f);
    }
    __syncthreads();
    ull y2[12];
    #pragma unroll
    for (int p=0;p<12;++p) y2[p]=pack2(0.f,0.f);
    const float* wp = W1 + 1024*UU + tx;
    #pragma unroll 2
    for (int k=0;k<256;++k){
        float w = wp[k*UU];
        ull w2 = pack2(w,w);
        #pragma unroll
        for (int p=0;p<12;++p) fma2(y2[p], *(const ull*)&se[k][2*p], w2);
    }
    float sp = g_s1[b][tx];
    float wo = w2v[tx];
    float ct[24];
    #pragma unroll
    for (int p=0;p<12;++p){
        float a0,a1; unpack2(y2[p],a0,a1);
        ct[2*p]   = fmaxf(sp+a0, 0.f)*wo;
        ct[2*p+1] = fmaxf(sp+a1, 0.f)*wo;
    }
    #pragma unroll
    for (int h=0;h<24;++h){
        #pragma unroll
        for (int o=16;o>0;o>>=1) ct[h] += __shfl_xor_sync(0xffffffffu, ct[h], o);
    }
    if (lane==0){
        #pragma unroll
        for (int h=0;h<24;++h) prt[wid][h] = ct[h];
    }
    __syncthreads();
    if (tx < 24){
        float s2 = b2[0];
        #pragma unroll
        for (int w=0;w<8;++w) s2 += prt[w][tx];
        out[b*HH + tx] = s2;
    }
}

extern "C" void kernel_launch(void* const* d_in, const int* in_sizes, int n_in,
                              void* d_out, int out_size){
    const float* enc_in = (const float*)d_in[0];
    const float* dec_in = (const float*)d_in[1];
    const float* ext_f  = (const float*)d_in[2];
    const float* enc_W  = (const float*)d_in[3];
    const float* enc_U  = (const float*)d_in[4];
    const float* enc_b  = (const float*)d_in[5];
    const float* att_W1 = (const float*)d_in[6];
    const float* att_W2 = (const float*)d_in[7];
    const float* att_v  = (const float*)d_in[8];
    const float* dec_W  = (const float*)d_in[9];
    const float* dec_U  = (const float*)d_in[10];
    const float* dec_b  = (const float*)d_in[11];
    const float* ext_W  = (const float*)d_in[12];
    const float* ext_b  = (const float*)d_in[13];
    const float* out1_W = (const float*)d_in[14];
    const float* out1_b = (const float*)d_in[15];
    const float* out2_W = (const float*)d_in[16];
    const float* out2_b = (const float*)d_in[17];
    float* out = (float*)d_out;

    const int enc_smem = E_TOT * 4;   // 186624 B
    cudaFuncSetAttribute(k_enc, cudaFuncAttributeMaxDynamicSharedMemorySize, enc_smem);
    cudaFuncSetAttribute(k_dA, cudaFuncAttributeMaxDynamicSharedMemorySize, A_SMEM);
    cudaFuncSetAttribute(k_dC, cudaFuncAttributeMaxDynamicSharedMemorySize, C_SMEM);

    k_init<<<768,  256>>>();
    k_enc <<<96,   256, enc_smem>>>(enc_in, enc_W, enc_U, enc_b);
    k_proj<<<8064, 256>>>(att_W1);

    for (int s = 0; s < HH; ++s){
        k_dA<<<128, 256, A_SMEM>>>(dec_W, dec_U);
        k_dB<<<256, 256>>>(dec_W, dec_b, dec_in, s);
        k_dC<<<96,  256, C_SMEM>>>(att_W2);
        k_dD<<<768, 256>>>(att_v);
    }

    k_h1<<<32,  256>>>(out1_W, out1_b);
    k_h2<<<256, 256>>>(ext_f, ext_W, ext_b, out1_W, out2_W, out2_b, out);
}

// round 12
// speedup vs baseline: 1.0435x; 1.0411x over previous
#include <cuda_runtime.h>
#include <cuda_bf16.h>

#define NE 3
#define BB 256
#define TT 168
#define DE 32
#define UU 256
#define U3 768
#define HH 24
#define BT (BB*TT)

typedef unsigned long long ull;

__device__ __forceinline__ ull pack2(float lo, float hi){ ull r; asm("mov.b64 %0,{%1,%2};":"=l"(r):"f"(lo),"f"(hi)); return r; }
__device__ __forceinline__ void unpack2(ull v, float&lo, float&hi){ asm("mov.b64 {%0,%1},%2;":"=f"(lo),"=f"(hi):"l"(v)); }
__device__ __forceinline__ void fma2(ull&d, ull a, ull b){ asm("fma.rn.f32x2 %0,%1,%2,%0;":"+l"(d):"l"(a),"l"(b)); }

__device__ __forceinline__ float sigm(float x){ return __fdividef(1.f, 1.f + __expf(-x)); }
__device__ __forceinline__ float tanh_(float x){
    float e = __expf(-2.f*fabsf(x));
    float t = __fdividef(1.f-e, 1.f+e);
    return copysignf(t,x);
}
__device__ __forceinline__ float tanha(float x){ float y; asm("tanh.approx.f32 %0,%1;":"=f"(y):"f"(x)); return y; }
__device__ __forceinline__ float blo(unsigned pk){ return __uint_as_float(pk << 16); }
__device__ __forceinline__ float bhi(unsigned pk){ return __uint_as_float(pk & 0xffff0000u); }

// ---------------- device scratch ----------------
__device__ __align__(16) __nv_bfloat16 g_eoh[NE][BT][UU]; // enc_out bf16
__device__ __align__(16) __nv_bfloat16 g_pjh[NE][BT][UU]; // enc_proj bf16
__device__ __align__(16) float g_h[2][NE][BB][UU];        // encoder hidden ping-pong
__device__ __align__(16) float g_hd[BB][UU];
__device__ __align__(16) float g_c[BB][U3];
__device__ __align__(16) float g_q[NE][BB][UU];
__device__ __align__(16) float g_dp[4][BB][U3];
__device__ __align__(16) float g_s1[BB][UU];
__device__ unsigned g_es[12];

__global__ void k_init(){
    int i = blockIdx.x*256 + threadIdx.x;   // 768*256 = 196608
    ((float*)g_h)[i] = 0.f;                  // zeros buffer 0 exactly (NE*BB*UU)
    if (i < BB*UU) ((float*)g_hd)[i] = 0.f;
    if (i < BB*U3) ((float*)g_c)[i]  = 0.f;
    if (i < 12)    g_es[i] = 0u;
}

// ---------------- encoder: SMEM-resident weights, 8-CTA group sync (R9, passing) ----------------
#define E_SWU 0
#define E_SWX 24576
#define E_SH  27648
#define E_SXI 44544
#define E_TOT 46656

__global__ __launch_bounds__(256,1) void k_enc(const float* __restrict__ X, const float* __restrict__ W,
                                               const float* __restrict__ Uw, const float* __restrict__ bv){
    extern __shared__ float sm[];
    float* swU = sm + E_SWU;
    float* swX = sm + E_SWX;
    float* sh  = sm + E_SH;
    float* sxi = sm + E_SXI;

    const int cid = blockIdx.x;
    const int n = cid >> 5, rem = cid & 31;
    const int r0 = (rem >> 3) * 64, u0 = (rem & 7) * 32;
    const int gid = n*4 + (rem >> 3);
    const int tx = threadIdx.x, ul = tx & 31, grp = tx >> 5;

    for (int idx = tx; idx < 24576; idx += 256){
        int k = idx / 96, c = idx % 96;
        int g = c >> 5, cc = c & 31;
        swU[idx] = Uw[(size_t)n*UU*U3 + (size_t)k*U3 + g*256 + u0 + cc];
    }
    for (int idx = tx; idx < 3072; idx += 256){
        int k = idx / 96, c = idx % 96;
        int g = c >> 5, cc = c & 31;
        swX[idx] = W[(size_t)n*DE*U3 + (size_t)k*U3 + g*256 + u0 + cc];
    }
    const float bz = bv[n*U3 + u0+ul];
    const float br = bv[n*U3 + 256 + u0+ul];
    const float bn = bv[n*U3 + 512 + u0+ul];
    __syncthreads();

    __nv_bfloat16* eob = &g_eoh[n][0][0];

    for (int t = 0; t < TT; ++t){
        const float* hs = &g_h[t&1][n][0][0];
        #pragma unroll 8
        for (int i = 0; i < 64; ++i) sh[tx*66 + i] = __ldcg(hs + (size_t)(r0+i)*UU + tx);
        {
            int idx = tx;
            #pragma unroll
            for (int i = 0; i < 8; ++i, idx += 256){
                int row = idx >> 5, col = idx & 31;
                sxi[col*66 + row] = X[(((size_t)n*BB + r0+row)*TT + t)*DE + col];
            }
        }
        __syncthreads();

        ull az[4], ar[4], ax[4], ah[4];
        #pragma unroll
        for (int j=0;j<4;++j){ az[j]=pack2(bz,bz); ar[j]=pack2(br,br); ax[j]=pack2(bn,bn); ah[j]=pack2(0.f,0.f); }

        #pragma unroll 4
        for (int k = 0; k < 256; ++k){
            const float* wrow = swU + k*96;
            float wza = wrow[ul], wra = wrow[32+ul], wna = wrow[64+ul];
            ull wz = pack2(wza,wza), wr = pack2(wra,wra), wn = pack2(wna,wna);
            const float* hrow = sh + k*66 + grp*8;
            #pragma unroll
            for (int j=0;j<4;++j){
                ull h2 = *(const ull*)&hrow[2*j];
                fma2(az[j],h2,wz); fma2(ar[j],h2,wr); fma2(ah[j],h2,wn);
            }
        }
        #pragma unroll 4
        for (int k = 0; k < 32; ++k){
            const float* wrow = swX + k*96;
            float wza = wrow[ul], wra = wrow[32+ul], wna = wrow[64+ul];
            ull wz = pack2(wza,wza), wr = pack2(wra,wra), wn = pack2(wna,wna);
            const float* xrow = sxi + k*66 + grp*8;
            #pragma unroll
            for (int j=0;j<4;++j){
                ull x2 = *(const ull*)&xrow[2*j];
                fma2(az[j],x2,wz); fma2(ar[j],x2,wr); fma2(ax[j],x2,wn);
            }
        }

        float* hd = &g_h[(t+1)&1][n][0][0];
        #pragma unroll
        for (int j=0;j<4;++j){
            int rl = grp*8 + 2*j;
            float z0,z1,rg0,rg1,x0,x1,hh0,hh1;
            unpack2(az[j],z0,z1); unpack2(ar[j],rg0,rg1); unpack2(ax[j],x0,x1); unpack2(ah[j],hh0,hh1);
            float hp0 = sh[(u0+ul)*66 + rl];
            float hp1 = sh[(u0+ul)*66 + rl + 1];
            z0=sigm(z0); z1=sigm(z1); rg0=sigm(rg0); rg1=sigm(rg1);
            float n0 = tanh_(x0 + rg0*hh0), n1 = tanh_(x1 + rg1*hh1);
            float o0 = (1.f-z0)*hp0 + z0*n0;
            float o1 = (1.f-z1)*hp1 + z1*n1;
            hd[(size_t)(r0+rl)*UU + u0+ul]   = o0;
            hd[(size_t)(r0+rl+1)*UU + u0+ul] = o1;
            eob[((size_t)(r0+rl)*TT + t)*UU + u0+ul]   = __float2bfloat16_rn(o0);
            eob[((size_t)(r0+rl+1)*TT + t)*UU + u0+ul] = __float2bfloat16_rn(o1);
        }

        __threadfence();
        __syncthreads();
        if (tx == 0){
            atomicAdd(&g_es[gid], 1u);
            unsigned tgt = 8u*(unsigned)(t+1);
            while (*((volatile unsigned*)&g_es[gid]) < tgt) { }
        }
        __syncthreads();
    }
}

// ---------------- enc_proj GEMM: 8x2 register tile (measured 480us) ----------------
__global__ __launch_bounds__(256) void k_proj(const float* __restrict__ W1){
    const int cid = blockIdx.x;                 // 8064
    const int n = cid / 2688, rem = cid % 2688;
    const int r0 = (rem >> 2) * 64, j0 = (rem & 3) * 64;
    const int tx = threadIdx.x;
    const int ty = tx >> 5;
    const int tix = tx & 31;

    __shared__ __align__(16) float sa[64][66];
    __shared__ __align__(16) float sb[64][66];

    const __nv_bfloat16* A = &g_eoh[n][0][0];
    const float* Bw = W1 + (size_t)n*UU*UU;

    ull acc[4][2];
    #pragma unroll
    for (int rp=0;rp<4;++rp){ acc[rp][0]=pack2(0.f,0.f); acc[rp][1]=pack2(0.f,0.f); }

    for (int kc=0;kc<4;++kc){
        {
            int idx = tx;
            #pragma unroll
            for (int i=0;i<16;++i, idx+=256){
                int row = idx>>6, k = idx&63;
                sa[k][row] = __bfloat162float(A[(size_t)(r0+row)*UU + kc*64 + k]);
            }
            idx = tx;
            #pragma unroll
            for (int i=0;i<16;++i, idx+=256){
                int k = idx>>6, col = idx&63;
                sb[k][col] = Bw[(size_t)(kc*64+k)*UU + j0 + col];
            }
        }
        __syncthreads();
        #pragma unroll 2
        for (int k=0;k<64;++k){
            const float* ar = &sa[k][ty*8];
            ull a0 = *(const ull*)(ar+0);
            ull a1 = *(const ull*)(ar+2);
            ull a2 = *(const ull*)(ar+4);
            ull a3 = *(const ull*)(ar+6);
            ull bp = *(const ull*)&sb[k][tix*2];
            float b0,b1; unpack2(bp,b0,b1);
            ull w0 = pack2(b0,b0), w1 = pack2(b1,b1);
            fma2(acc[0][0],a0,w0); fma2(acc[0][1],a0,w1);
            fma2(acc[1][0],a1,w0); fma2(acc[1][1],a1,w1);
            fma2(acc[2][0],a2,w0); fma2(acc[2][1],a2,w1);
            fma2(acc[3][0],a3,w0); fma2(acc[3][1],a3,w1);
        }
        __syncthreads();
    }
    __nv_bfloat16* C = &g_pjh[n][0][0];
    #pragma unroll
    for (int rp=0;rp<4;++rp){
        float r0c0, r1c0, r0c1, r1c1;
        unpack2(acc[rp][0], r0c0, r1c0);
        unpack2(acc[rp][1], r0c1, r1c1);
        int rowA = r0 + ty*8 + 2*rp;
        float2 f0; f0.x = r0c0; f0.y = r0c1;
        float2 f1; f1.x = r1c0; f1.y = r1c1;
        *(__nv_bfloat162*)&C[(size_t)rowA*UU + j0 + tix*2]     = __float22bfloat162_rn(f0);
        *(__nv_bfloat162*)&C[(size_t)(rowA+1)*UU + j0 + tix*2] = __float22bfloat162_rn(f1);
    }
}

// ================= decoder: 4 kernels per step =================

// ---- A: K-split GRU GEMM (grid 128), float4 weight staging (measured 25.1us) ----
#define A_SMEM ((24576+16896)*4)
__global__ __launch_bounds__(256,1) void k_dA(const float* __restrict__ dW, const float* __restrict__ dU){
    extern __shared__ float sm[];
    float* swD = sm;
    float* sh  = sm + 24576;

    const int cid = blockIdx.x;
    const int tx = threadIdx.x;
    const int ul = tx & 31, grp = tx >> 5;
    const int kt  = cid >> 5;
    const int rem = cid & 31;
    const int r0  = (rem >> 3) * 64, u0 = (rem & 7) * 32;

    const float* wb = (kt < 3) ? (dW + (size_t)kt*256*U3) : dU;
    for (int idx = tx; idx < 6144; idx += 256){
        int k = idx / 24, c4 = idx - k*24;
        int col = c4*4, g = col >> 5, cc = col & 31;
        *(float4*)&swD[k*96 + col] = *(const float4*)(wb + (size_t)k*U3 + g*256 + u0 + cc);
    }
    const float* src; int stride, koff;
    if (kt < 3){ src = &g_c[0][0]; stride = U3; koff = kt*256; }
    else       { src = &g_hd[0][0]; stride = UU; koff = 0; }
    #pragma unroll 8
    for (int i = 0; i < 64; ++i) sh[tx*66 + i] = src[(size_t)(r0+i)*stride + koff + tx];
    __syncthreads();

    ull az[4], ar[4], an[4];
    #pragma unroll
    for (int j=0;j<4;++j){ az[j]=pack2(0.f,0.f); ar[j]=pack2(0.f,0.f); an[j]=pack2(0.f,0.f); }
    #pragma unroll 2
    for (int k = 0; k < 256; ++k){
        const float* wrow = swD + k*96;
        float wza = wrow[ul], wra = wrow[32+ul], wna = wrow[64+ul];
        ull wz = pack2(wza,wza), wr = pack2(wra,wra), wn = pack2(wna,wna);
        const float* hrow = sh + k*66 + grp*8;
        #pragma unroll
        for (int j=0;j<4;++j){
            ull h2 = *(const ull*)&hrow[2*j];
            fma2(az[j],h2,wz); fma2(ar[j],h2,wr); fma2(an[j],h2,wn);
        }
    }
    float* dp = &g_dp[kt][0][0];
    #pragma unroll
    for (int j=0;j<4;++j){
        int rl = grp*8 + 2*j; float a0,a1;
        unpack2(az[j],a0,a1); dp[(r0+rl)*U3 + u0+ul] = a0;       dp[(r0+rl+1)*U3 + u0+ul] = a1;
        unpack2(ar[j],a0,a1); dp[(r0+rl)*U3 + 256 + u0+ul] = a0; dp[(r0+rl+1)*U3 + 256 + u0+ul] = a1;
        unpack2(an[j],a0,a1); dp[(r0+rl)*U3 + 512 + u0+ul] = a0; dp[(r0+rl+1)*U3 + 512 + u0+ul] = a1;
    }
}

// ---- B: reduce partials + pointwise GRU (grid 256) ----
__global__ __launch_bounds__(256) void k_dB(const float* __restrict__ dW, const float* __restrict__ db,
                                            const float* __restrict__ dinp, int s){
    int r = blockIdx.x, u = threadIdx.x;
    float d  = dinp[r*HH + s];
    float zp = db[u]     + d*dW[(size_t)768*U3 + u];
    float rp = db[256+u] + d*dW[(size_t)768*U3 + 256+u];
    float nx = db[512+u] + d*dW[(size_t)768*U3 + 512+u];
    float nh = g_dp[3][r][512+u];
    zp += g_dp[0][r][u] + g_dp[1][r][u] + g_dp[2][r][u] + g_dp[3][r][u];
    rp += g_dp[0][r][256+u] + g_dp[1][r][256+u] + g_dp[2][r][256+u] + g_dp[3][r][256+u];
    nx += g_dp[0][r][512+u] + g_dp[1][r][512+u] + g_dp[2][r][512+u];
    float z = sigm(zp), rg = sigm(rp);
    float nn = tanh_(nx + rg*nh);
    float hp = g_hd[r][u];
    g_hd[r][u] = (1.f-z)*hp + z*nn;
}

// ---- C: q = h @ att_W2 (grid 96), float4 weight staging ----
#define C_SMEM ((8192+16896)*4)
__global__ __launch_bounds__(256,1) void k_dC(const float* __restrict__ W2){
    extern __shared__ float sm[];
    float* sw2 = sm;
    float* sh  = sm + 8192;

    const int cid = blockIdx.x;
    const int tx = threadIdx.x;
    const int ul = tx & 31, grp = tx >> 5;
    const int n2 = cid >> 5;
    const int rm = cid & 31;
    const int rr0 = (rm >> 3) * 64, v0 = (rm & 7) * 32;

    for (int idx = tx; idx < 2048; idx += 256){
        int k = idx >> 3, c4 = idx & 7;
        *(float4*)&sw2[k*32 + c4*4] =
            *(const float4*)(W2 + (size_t)n2*UU*UU + (size_t)k*UU + v0 + c4*4);
    }
    #pragma unroll 8
    for (int i = 0; i < 64; ++i) sh[tx*66 + i] = g_hd[rr0+i][tx];
    __syncthreads();

    ull ac[4];
    #pragma unroll
    for (int j=0;j<4;++j) ac[j] = pack2(0.f,0.f);
    #pragma unroll 2
    for (int k = 0; k < 256; ++k){
        float w = sw2[k*32 + ul];
        ull w2 = pack2(w,w);
        const float* hrow = sh + k*66 + grp*8;
        #pragma unroll
        for (int j=0;j<4;++j) fma2(ac[j], *(const ull*)&hrow[2*j], w2);
    }
    #pragma unroll
    for (int j=0;j<4;++j){
        int rl = grp*8 + 2*j; float a0,a1; unpack2(ac[j],a0,a1);
        g_q[n2][rr0+rl][v0+ul]   = a0;
        g_q[n2][rr0+rl+1][v0+ul] = a1;
    }
}

// ---- D: attention (R9 version — best measured config) ----
__global__ __launch_bounds__(256) void k_dD(const float* __restrict__ av){
    __shared__ __align__(16) float q_s[256], v_s[256];
    __shared__ float sc_s[176];
    __shared__ __align__(16) float sred[1024];

    const int tx = threadIdx.x, lane = tx & 31, wid = tx >> 5;
    const int n3 = blockIdx.x >> 8, b = blockIdx.x & 255;

    q_s[tx] = g_q[n3][b][tx];
    v_s[tx] = av[n3*UU + tx];
    __syncthreads();

    const __nv_bfloat16* pj = &g_pjh[n3][0][0] + (size_t)b*TT*UU;
    #pragma unroll 3
    for (int ii = 0; ii < 21; ++ii){
        int t = wid*21 + ii;
        const uint2* row = (const uint2*)(pj + (size_t)t*UU);
        float acc = 0.f;
        #pragma unroll
        for (int j2 = 0; j2 < 2; ++j2){
            int v = j2*128 + 4*lane;
            uint2 pk = row[j2*32 + lane];
            float4 qv = *(const float4*)&q_s[v];
            float4 vv = *(const float4*)&v_s[v];
            acc += tanha(blo(pk.x) + qv.x) * vv.x;
            acc += tanha(bhi(pk.x) + qv.y) * vv.y;
            acc += tanha(blo(pk.y) + qv.z) * vv.z;
            acc += tanha(bhi(pk.y) + qv.w) * vv.w;
        }
        #pragma unroll
        for (int o = 16; o > 0; o >>= 1) acc += __shfl_xor_sync(0xffffffffu, acc, o);
        if (lane == 0) sc_s[t] = acc;
    }
    __syncthreads();
    if (wid == 0){
        float m = -1e30f;
        for (int t = lane; t < TT; t += 32) m = fmaxf(m, sc_s[t]);
        #pragma unroll
        for (int o = 16; o > 0; o >>= 1) m = fmaxf(m, __shfl_xor_sync(0xffffffffu, m, o));
        float ss = 0.f;
        for (int t = lane; t < TT; t += 32){ float e2 = __expf(sc_s[t]-m); sc_s[t] = e2; ss += e2; }
        #pragma unroll
        for (int o = 16; o > 0; o >>= 1) ss += __shfl_xor_sync(0xffffffffu, ss, o);
        float inv = __fdividef(1.f, ss);
        for (int t = lane; t < TT; t += 32) sc_s[t] *= inv;
    }
    __syncthreads();
    {
        int tg = tx >> 6, uq = tx & 63;
        const __nv_bfloat16* eob = &g_eoh[n3][0][0] + (size_t)b*TT*UU;
        float4 a = make_float4(0.f,0.f,0.f,0.f);
        #pragma unroll 6
        for (int i = 0; i < 42; ++i){
            int t = tg + 4*i;
            uint2 e = __ldcs((const uint2*)(eob + (size_t)t*UU) + uq);
            float w = sc_s[t];
            a.x += w*blo(e.x); a.y += w*bhi(e.x);
            a.z += w*blo(e.y); a.w += w*bhi(e.y);
        }
        ((float4*)sred)[tg*64 + uq] = a;
    }
    __syncthreads();
    {
        int uq = tx >> 2, comp = tx & 3;
        float sum = sred[(0*64 + uq)*4 + comp] + sred[(1*64 + uq)*4 + comp]
                  + sred[(2*64 + uq)*4 + comp] + sred[(3*64 + uq)*4 + comp];
        g_c[b][n3*UU + tx] = sum;
    }
}

// ---------------- head part 1 ----------------
__global__ __launch_bounds__(256) void k_h1(const float* __restrict__ W1, const float* __restrict__ b1){
    const int rem = blockIdx.x;          // 32
    const int r0 = (rem>>2)*32, j0 = (rem&3)*64;
    const int tx = threadIdx.x, ul = tx&63, grp = tx>>6;
    __shared__ __align__(16) float sh[256][34];
    ull acc[4];
    #pragma unroll
    for (int j=0;j<4;++j) acc[j]=pack2(0.f,0.f);
    for (int cc=0;cc<4;++cc){
        const float* src = (cc==0) ? &g_hd[0][0] : (&g_c[0][0] + (cc-1)*256);
        int stride = (cc==0) ? UU : U3;
        __syncthreads();
        #pragma unroll 8
        for (int i=0;i<32;++i) sh[tx][i] = src[(r0+i)*stride + tx];
        __syncthreads();
        const float* wp = W1 + cc*256*UU + j0 + ul;
        #pragma unroll 2
        for (int k=0;k<256;++k){
            float w = wp[k*UU];
            ull w2 = pack2(w,w);
            #pragma unroll
            for (int j=0;j<4;++j) fma2(acc[j], *(const ull*)&sh[k][(grp*4+j)*2], w2);
        }
    }
    float bb = b1[j0+ul];
    #pragma unroll
    for (int j=0;j<4;++j){
        int rl=(grp*4+j)*2; float a0,a1; unpack2(acc[j],a0,a1);
        g_s1[r0+rl][j0+ul]   = a0+bb;
        g_s1[r0+rl+1][j0+ul] = a1+bb;
    }
}

// ---------------- head part 2 ----------------
__global__ __launch_bounds__(256) void k_h2(const float* __restrict__ ef, const float* __restrict__ eW,
        const float* __restrict__ eb, const float* __restrict__ W1, const float* __restrict__ w2v,
        const float* __restrict__ b2, float* __restrict__ out){
    const int b = blockIdx.x, tx = threadIdx.x, lane = tx&31, wid = tx>>5;
    __shared__ __align__(16) float se[256][26];
    __shared__ float sf[384];
    __shared__ float prt[8][24];
    sf[tx < 384 ? tx : 0] = ef[b*384 + (tx < 384 ? tx : 0)];
    if (tx < 128) sf[256+tx] = ef[b*384 + 256 + tx];
    __syncthreads();
    float wk[16];
    #pragma unroll
    for (int k=0;k<16;++k) wk[k] = eW[k*UU + tx];
    float ebv = eb[tx];
    #pragma unroll
    for (int h=0;h<24;++h){
        float a = ebv;
        #pragma unroll
        for (int k=0;k<16;++k) a += sf[h*16+k]*wk[k];
        se[tx][h] = fmaxf(a, 0.f);
    }
    __syncthreads();
    ull y2[12];
    #pragma unroll
    for (int p=0;p<12;++p) y2[p]=pack2(0.f,0.f);
    const float* wp = W1 + 1024*UU + tx;
    #pragma unroll 2
    for (int k=0;k<256;++k){
        float w = wp[k*UU];
        ull w2 = pack2(w,w);
        #pragma unroll
        for (int p=0;p<12;++p) fma2(y2[p], *(const ull*)&se[k][2*p], w2);
    }
    float sp = g_s1[b][tx];
    float wo = w2v[tx];
    float ct[24];
    #pragma unroll
    for (int p=0;p<12;++p){
        float a0,a1; unpack2(y2[p],a0,a1);
        ct[2*p]   = fmaxf(sp+a0, 0.f)*wo;
        ct[2*p+1] = fmaxf(sp+a1, 0.f)*wo;
    }
    #pragma unroll
    for (int h=0;h<24;++h){
        #pragma unroll
        for (int o=16;o>0;o>>=1) ct[h] += __shfl_xor_sync(0xffffffffu, ct[h], o);
    }
    if (lane==0){
        #pragma unroll
        for (int h=0;h<24;++h) prt[wid][h] = ct[h];
    }
    __syncthreads();
    if (tx < 24){
        float s2 = b2[0];
        #pragma unroll
        for (int w=0;w<8;++w) s2 += prt[w][tx];
        out[b*HH + tx] = s2;
    }
}

extern "C" void kernel_launch(void* const* d_in, const int* in_sizes, int n_in,
                              void* d_out, int out_size){
    const float* enc_in = (const float*)d_in[0];
    const float* dec_in = (const float*)d_in[1];
    const float* ext_f  = (const float*)d_in[2];
    const float* enc_W  = (const float*)d_in[3];
    const float* enc_U  = (const float*)d_in[4];
    const float* enc_b  = (const float*)d_in[5];
    const float* att_W1 = (const float*)d_in[6];
    const float* att_W2 = (const float*)d_in[7];
    const float* att_v  = (const float*)d_in[8];
    const float* dec_W  = (const float*)d_in[9];
    const float* dec_U  = (const float*)d_in[10];
    const float* dec_b  = (const float*)d_in[11];
    const float* ext_W  = (const float*)d_in[12];
    const float* ext_b  = (const float*)d_in[13];
    const float* out1_W = (const float*)d_in[14];
    const float* out1_b = (const float*)d_in[15];
    const float* out2_W = (const float*)d_in[16];
    const float* out2_b = (const float*)d_in[17];
    float* out = (float*)d_out;

    const int enc_smem = E_TOT * 4;   // 186624 B
    cudaFuncSetAttribute(k_enc, cudaFuncAttributeMaxDynamicSharedMemorySize, enc_smem);
    cudaFuncSetAttribute(k_dA, cudaFuncAttributeMaxDynamicSharedMemorySize, A_SMEM);
    cudaFuncSetAttribute(k_dC, cudaFuncAttributeMaxDynamicSharedMemorySize, C_SMEM);

    k_init<<<768,  256>>>();
    k_enc <<<96,   256, enc_smem>>>(enc_in, enc_W, enc_U, enc_b);
    k_proj<<<8064, 256>>>(att_W1);

    for (int s = 0; s < HH; ++s){
        k_dA<<<128, 256, A_SMEM>>>(dec_W, dec_U);
        k_dB<<<256, 256>>>(dec_W, dec_b, dec_in, s);
        k_dC<<<96,  256, C_SMEM>>>(att_W2);
        k_dD<<<768, 256>>>(att_v);
    }

    k_h1<<<32,  256>>>(out1_W, out1_b);
    k_h2<<<256, 256>>>(ext_f, ext_W, ext_b, out1_W, out2_W, out2_b, out);
}